// round 6
// baseline (speedup 1.0000x reference)
#include <cuda_runtime.h>
#include <cstdint>

#define BB 32
#define IC 256
#define OC 512
#define HW 56
#define NPIX (HW*HW)
#define NF 64

// scratch (no allocations allowed)
__device__ float g_pooled[BB*IC];

__device__ __forceinline__ float to_tf32(float v){
    float o; asm("cvt.rna.tf32.f32 %0, %1;" : "=f"(o) : "f"(v)); return o;
}

// ---------------------------------------------------------------------------
// Kernel 1: global average pool.
// ---------------------------------------------------------------------------
__global__ void pool_kernel(const float* __restrict__ x) {
    int plane = blockIdx.x;
    const float4* p = (const float4*)(x + (size_t)plane * NPIX);
    float s = 0.f;
    for (int i = threadIdx.x; i < NPIX/4; i += 128) {
        float4 v = p[i];
        s += (v.x + v.y) + (v.z + v.w);
    }
    #pragma unroll
    for (int o = 16; o; o >>= 1) s += __shfl_down_sync(0xffffffffu, s, o);
    __shared__ float ws[4];
    if ((threadIdx.x & 31) == 0) ws[threadIdx.x >> 5] = s;
    __syncthreads();
    if (threadIdx.x == 0)
        g_pooled[plane] = (ws[0] + ws[1] + ws[2] + ws[3]) * (1.0f / NPIX);
}

// ---------------------------------------------------------------------------
// Kernel 2: fused router + tf32 mma.sync implicit-GEMM conv.
// Each CTA recomputes the top-64 selection for its batch sample (bitwise
// deterministic; column order does not affect per-oc accumulation order).
// CTA = (b, 8-row slab, 28-col half).  Grid (7, 2, 32), 256 threads.
// Warp = M32 x N64 (one output row).  2 CTAs/SM.
// Window smem: [y 10][x 34][ic-slot 40].  B: 4-slot ring, sync per 2 taps,
// LDG prefetch distance 2, STS after compute (latency hidden).
// ---------------------------------------------------------------------------
#define XP 34
#define WIN_FLOATS (10*XP*40)
#define BSTG 2560
#define SMEMB ((WIN_FLOATS + 4*BSTG)*4)

__global__ __launch_bounds__(256, 2)
void conv_mma(const float* __restrict__ x, const float* __restrict__ w,
              const float* __restrict__ bias,
              const float* __restrict__ rw, const float* __restrict__ rb,
              float* __restrict__ out)
{
    extern __shared__ float sm[];
    float* win = sm;
    float* Bst = sm + WIN_FLOATS;
    __shared__ float s_ps[IC];
    __shared__ float s_rs[OC];
    __shared__ int   s_sel[64];
    __shared__ float s_bias[64];
    __shared__ int   s_cnt;

    const int tid  = threadIdx.x;
    const int w8   = tid >> 5;            // warp id == output row within slab
    const int lane = tid & 31;
    const int g    = lane >> 2;           // mma groupID
    const int tq   = lane & 3;            // mma threadID-in-group
    const int r0   = blockIdx.x * 8;
    const int xoff = blockIdx.y * 28;
    const int b    = blockIdx.z;

    // ---- router (redundant per CTA) ----
    if (tid == 0) s_cnt = 0;
    s_ps[tid] = g_pooled[b*IC + tid];
    // zero window once (halo/pad cells never rewritten)
    for (int i = tid; i < WIN_FLOATS/4; i += 256)
        ((float4*)win)[i] = make_float4(0.f,0.f,0.f,0.f);
    __syncthreads();
    #pragma unroll
    for (int h = 0; h < 2; h++) {
        int oc = tid + 256*h;
        float s = rb[oc];
        const float* wr = rw + (size_t)oc * IC;
        #pragma unroll 8
        for (int i = 0; i < IC; i++) s += s_ps[i] * wr[i];
        s_rs[oc] = s;
    }
    __syncthreads();
    #pragma unroll
    for (int h = 0; h < 2; h++) {
        int oc = tid + 256*h;
        float s = s_rs[oc];
        int rank = 0;
        for (int j = 0; j < OC; j++) {
            float v = s_rs[j];
            rank += (v > s) || (v == s && j < oc);
        }
        if (rank < NF) {
            int pos = atomicAdd(&s_cnt, 1);
            s_sel[pos] = oc;
        }
    }
    __syncthreads();
    if (tid < 64) s_bias[tid] = bias[s_sel[tid]];
    __syncthreads();

    const float* xb   = x + (size_t)b*IC*NPIX;
    float*       outb = out + (size_t)b*OC*NPIX;

    // ---- B fill mapping: thread -> oc = fg+8*w8, ic' = ftk + 4e ----
    const int ftk = tid & 3;
    const int fg  = (tid >> 2) & 7;
    const int foc = fg + 8*w8;
    const float* wrow = w + (size_t)s_sel[foc]*(IC*9);
    float wp[8];

    #define LDG_B(icg_, tap_) do {                                          \
        const float* p_ = wrow + (size_t)((icg_)*32 + ftk)*9 + (tap_);      \
        _Pragma("unroll")                                                   \
        for (int e = 0; e < 8; e++) wp[e] = p_[36*e];                       \
    } while(0)

    #define STS_B(buf_) do {                                                \
        float* d_ = Bst + (buf_)*BSTG + foc*40 + 2*ftk;                     \
        _Pragma("unroll")                                                   \
        for (int e = 0; e < 8; e++)                                         \
            d_[8*(e>>1) + (e&1)] = to_tf32(wp[e]);                          \
    } while(0)

    // ---- window fill: 10 y x 30 x x 32 ic = 9600 elements per ic-group ----
    #define FILL_WIN(icg_) do {                                             \
        for (int i = tid; i < 9600; i += 256) {                             \
            int icsub = i & 3;                                              \
            int t2 = i >> 2;                                                \
            int xx = t2 % 30;                                               \
            int t3 = t2 / 30;                                               \
            int icq = t3 & 7;                                               \
            int y   = t3 >> 3;                                              \
            int icl = icsub + 4*icq;                                        \
            int gy  = r0 - 1 + y;                                           \
            int gx  = xoff + xx - 1;                                        \
            float v = 0.f;                                                  \
            if ((unsigned)gy < (unsigned)HW && (unsigned)gx < (unsigned)HW) \
                v = xb[(size_t)((icg_)*32 + icl)*NPIX + gy*HW + gx];        \
            int slot = 8*(icq>>1) + 2*icsub + (icq&1);                      \
            win[(y*XP + xx)*40 + slot] = to_tf32(v);                        \
        }                                                                   \
    } while(0)

    float acc[2][8][4];
    #pragma unroll
    for (int mt = 0; mt < 2; mt++)
        #pragma unroll
        for (int nt = 0; nt < 8; nt++)
            #pragma unroll
            for (int q = 0; q < 4; q++) acc[mt][nt][q] = 0.f;

    // one tap: LDG(c+2) -> zero-fill -> mma(c) -> STS(c+2)
    #define DO_TAP(tap_) do {                                               \
        const int c_ = cbase + (tap_);                                      \
        const bool pf_ = (c_ + 2 < 72);                                     \
        if (pf_) {                                                          \
            int nc_ = c_ + 2;                                               \
            int ni_ = nc_ / 9;                                              \
            LDG_B(ni_, nc_ - 9*ni_);                                        \
        }                                                                   \
        _Pragma("unroll")                                                   \
        for (int zz = 0; zz < 2; zz++) {                                    \
            int v_ = (c_*2 + zz)*256 + tid;                                 \
            if (v_ < 28672) {                                               \
                int oc_  = v_ / 56;                                         \
                int rem_ = v_ - oc_*56;                                     \
                int rr_  = rem_ / 7;                                        \
                int c4_  = rem_ - rr_*7;                                    \
                *(float4*)(outb + (size_t)oc_*NPIX + (r0+rr_)*HW + xoff + c4_*4) \
                    = make_float4(0.f,0.f,0.f,0.f);                         \
            }                                                               \
        }                                                                   \
        const int dy_ = (tap_)/3 - 1;                                       \
        const int dx_ = (tap_) - 3*((tap_)/3) - 1;                          \
        const float* Ab = win + ((w8 + dy_ + 1)*XP + (dx_ + 1) + g)*40 + 2*tq; \
        const float* Bb = Bst + (c_ & 3)*BSTG + g*40 + 2*tq;                \
        _Pragma("unroll")                                                   \
        for (int ks = 0; ks < 4; ks++) {                                    \
            uint2 bf[8];                                                    \
            _Pragma("unroll")                                               \
            for (int nt = 0; nt < 8; nt++)                                  \
                bf[nt] = *(const uint2*)(Bb + nt*320 + ks*8);               \
            _Pragma("unroll")                                               \
            for (int mt = 0; mt < 2; mt++) {                                \
                uint2 aA = *(const uint2*)(Ab + mt*640 + ks*8);             \
                uint2 aB = *(const uint2*)(Ab + mt*640 + 320 + ks*8);       \
                _Pragma("unroll")                                           \
                for (int nt = 0; nt < 8; nt++) {                            \
                    asm volatile(                                           \
                      "mma.sync.aligned.m16n8k8.row.col.f32.tf32.tf32.f32 " \
                      "{%0,%1,%2,%3}, {%4,%5,%6,%7}, {%8,%9}, {%0,%1,%2,%3};" \
                      : "+f"(acc[mt][nt][0]), "+f"(acc[mt][nt][1]),         \
                        "+f"(acc[mt][nt][2]), "+f"(acc[mt][nt][3])          \
                      : "r"(aA.x), "r"(aB.x), "r"(aA.y), "r"(aB.y),         \
                        "r"(bf[nt].x), "r"(bf[nt].y));                      \
                }                                                           \
            }                                                               \
        }                                                                   \
        if (pf_) STS_B((c_ + 2) & 3);                                       \
    } while(0)

    // prologue: window icg0 + B chunks 0,1
    FILL_WIN(0);
    LDG_B(0, 0); STS_B(0);
    LDG_B(0, 1); STS_B(1);
    __syncthreads();

    for (int icg = 0; icg < 8; icg++) {
        const int cbase = icg * 9;
        if (icg) { FILL_WIN(icg); __syncthreads(); }
        DO_TAP(0); DO_TAP(1); __syncthreads();
        DO_TAP(2); DO_TAP(3); __syncthreads();
        DO_TAP(4); DO_TAP(5); __syncthreads();
        DO_TAP(6); DO_TAP(7); __syncthreads();
        DO_TAP(8);
        if (icg < 7) __syncthreads();     // window reuse barrier
    }

    // epilogue: warp w8 -> output row r0+w8, cols xoff + (mt*16+g), valid < 28
    {
        float* orow = outb + (r0 + w8)*HW + xoff;
        #pragma unroll
        for (int nt = 0; nt < 8; nt++) {
            #pragma unroll
            for (int hh = 0; hh < 2; hh++) {
                int n = nt*8 + tq*2 + hh;
                float* op = orow + (size_t)s_sel[n]*NPIX;
                float bi = s_bias[n];
                #pragma unroll
                for (int mt = 0; mt < 2; mt++) {
                    int col = mt*16 + g;
                    if (col < 28) {
                        op[col] = acc[mt][nt][hh] + bi;
                        int col8 = col + 8;
                        if (col8 < 28)
                            op[col8] = acc[mt][nt][2+hh] + bi;
                    }
                }
            }
        }
    }
}

// ---------------------------------------------------------------------------
extern "C" void kernel_launch(void* const* d_in, const int* in_sizes, int n_in,
                              void* d_out, int out_size) {
    const float* x    = (const float*)d_in[0];   // [32,256,56,56]
    const float* w    = (const float*)d_in[1];   // [512,256,3,3]
    const float* bias = (const float*)d_in[2];   // [512]
    const float* rw   = (const float*)d_in[3];   // [512,256]
    const float* rb   = (const float*)d_in[4];   // [512]
    float* out = (float*)d_out;                  // [32,512,56,56]

    cudaFuncSetAttribute(conv_mma, cudaFuncAttributeMaxDynamicSharedMemorySize,
                         SMEMB);

    pool_kernel<<<BB*IC, 128>>>(x);
    conv_mma<<<dim3(7, 2, BB), 256, SMEMB>>>(x, w, bias, rw, rb, out);
}

// round 8
// speedup vs baseline: 1.2794x; 1.2794x over previous
#include <cuda_runtime.h>
#include <cstdint>

#define BB 32
#define IC 256
#define OC 512
#define HW 56
#define NPIX (HW*HW)
#define NF 64

// scratch (no allocations allowed)
__device__ float g_pooled[BB*IC];
__device__ int   g_sel[BB*NF];

__device__ __forceinline__ float to_tf32(float v){
    float o; asm("cvt.rna.tf32.f32 %0, %1;" : "=f"(o) : "f"(v)); return o;
}

// ---------------------------------------------------------------------------
// Kernel 1: global average pool.
// ---------------------------------------------------------------------------
__global__ void pool_kernel(const float* __restrict__ x) {
    int plane = blockIdx.x;
    const float4* p = (const float4*)(x + (size_t)plane * NPIX);
    float s = 0.f;
    for (int i = threadIdx.x; i < NPIX/4; i += 128) {
        float4 v = p[i];
        s += (v.x + v.y) + (v.z + v.w);
    }
    #pragma unroll
    for (int o = 16; o; o >>= 1) s += __shfl_down_sync(0xffffffffu, s, o);
    __shared__ float ws[4];
    if ((threadIdx.x & 31) == 0) ws[threadIdx.x >> 5] = s;
    __syncthreads();
    if (threadIdx.x == 0)
        g_pooled[plane] = (ws[0] + ws[1] + ws[2] + ws[3]) * (1.0f / NPIX);
}

// ---------------------------------------------------------------------------
// Kernel 2: router linear + exact top-64 (tie-break by index, = jax top_k).
// ---------------------------------------------------------------------------
__global__ void router_kernel(const float* __restrict__ rw,
                              const float* __restrict__ rb) {
    int b  = blockIdx.x;
    int oc = threadIdx.x;
    __shared__ float ps[IC];
    __shared__ float rs[OC];
    __shared__ int   cnt;
    if (oc < IC) ps[oc] = g_pooled[b*IC + oc];
    if (oc == 0) cnt = 0;
    __syncthreads();
    float s = rb[oc];
    const float* wrow = rw + (size_t)oc * IC;
    #pragma unroll 8
    for (int i = 0; i < IC; i++) s += ps[i] * wrow[i];
    rs[oc] = s;
    __syncthreads();
    int rank = 0;
    for (int j = 0; j < OC; j++) {
        float v = rs[j];
        rank += (v > s) || (v == s && j < oc);
    }
    if (rank < NF) {
        int pos = atomicAdd(&cnt, 1);
        g_sel[b*NF + pos] = oc;
    }
}

// ---------------------------------------------------------------------------
// Kernel 3: tf32 mma.sync implicit-GEMM conv on the 64 selected channels.
// CTA = (b, 8-row slab, 28-col half-tile).  Grid (7, 2, 32), 256 threads.
// Warp = M32 x N64 (one output row).  2 CTAs/SM.
// Window smem: [y 10][x 34 pitch][ic-slot 40]; filled via coalesced LDG.128
// along x + STS.32 transpose scatter (tf32-converted).
// B smem: 2 x [oc 64][slot 40] double buffered per tap.
// Embedded zero-fill of all 512 oc for this CTA's 8x28 patch.
// ---------------------------------------------------------------------------
#define XP 34
#define WIN_FLOATS (10*XP*40)
#define BSTG 2560
#define SMEMB ((WIN_FLOATS + 2*BSTG)*4)

__global__ __launch_bounds__(256, 2)
void conv_mma(const float* __restrict__ x, const float* __restrict__ w,
              const float* __restrict__ bias, float* __restrict__ out)
{
    extern __shared__ float sm[];
    float* win = sm;
    float* Bst = sm + WIN_FLOATS;
    __shared__ int   s_sel[64];
    __shared__ float s_bias[64];

    const int tid  = threadIdx.x;
    const int w8   = tid >> 5;            // warp id == output row within slab
    const int lane = tid & 31;
    const int g    = lane >> 2;           // mma groupID
    const int tq   = lane & 3;            // mma threadID-in-group
    const int r0   = blockIdx.x * 8;
    const int xoff = blockIdx.y * 28;
    const int b    = blockIdx.z;

    if (tid < 64) {
        int sc = g_sel[b*NF + tid];
        s_sel[tid]  = sc;
        s_bias[tid] = bias[sc];
    }
    // zero window once (halo/pad cells never rewritten afterwards)
    for (int i = tid; i < WIN_FLOATS/4; i += 256)
        ((float4*)win)[i] = make_float4(0.f,0.f,0.f,0.f);
    __syncthreads();

    const float* xb   = x + (size_t)b*IC*NPIX;
    float*       outb = out + (size_t)b*OC*NPIX;

    // ---- B fill mapping: thread -> oc = fg+8*w8, ic' = ftk + 4e ----
    const int ftk = tid & 3;
    const int fg  = (tid >> 2) & 7;
    const int foc = fg + 8*w8;
    const float* wrow = w + (size_t)s_sel[foc]*(IC*9);
    float wp[8];

    #define LDG_B(icg_, tap_) do {                                          \
        const float* p_ = wrow + (size_t)((icg_)*32 + ftk)*9 + (tap_);      \
        _Pragma("unroll")                                                   \
        for (int e = 0; e < 8; e++) wp[e] = p_[36*e];                       \
    } while(0)

    #define STS_B(buf_) do {                                                \
        float* d_ = Bst + (buf_)*BSTG + foc*40 + 2*ftk;                     \
        _Pragma("unroll")                                                   \
        for (int e = 0; e < 8; e++)                                         \
            d_[8*(e>>1) + (e&1)] = to_tf32(wp[e]);                          \
    } while(0)

    // ---- window fill: coalesced LDG.128 + transpose scatter.
    // work item i -> (y 0..9, icl 0..31, j 0..8); loads aligned float4 at
    // gx4 = xoff-4+4j; stores up to 4 tf32 values at window x = 4j-3+q.
    #define FILL_WIN(icg_) do {                                             \
        const float* xp_ = xb + (size_t)(icg_)*32*NPIX;                     \
        for (int i = tid; i < 2880; i += 256) {                             \
            int j   = i % 9;                                                \
            int t2  = i / 9;                                                \
            int icl = t2 & 31;                                              \
            int y   = t2 >> 5;                                              \
            int gy  = r0 - 1 + y;                                           \
            int gx4 = xoff - 4 + 4*j;                                       \
            if ((unsigned)gy >= (unsigned)HW ||                             \
                (unsigned)gx4 > (unsigned)(HW-4)) continue;                 \
            float4 v = *(const float4*)(xp_ + (size_t)icl*NPIX + gy*HW + gx4); \
            int slot = 8*(icl>>3) + 2*(icl&3) + ((icl>>2)&1);               \
            float* wb_ = win + y*(XP*40) + slot;                            \
            int xx = 4*j - 3;                                               \
            if ((unsigned)xx < 30u) wb_[xx*40]     = to_tf32(v.x);          \
            if ((unsigned)(xx+1) < 30u) wb_[(xx+1)*40] = to_tf32(v.y);      \
            if ((unsigned)(xx+2) < 30u) wb_[(xx+2)*40] = to_tf32(v.z);      \
            if ((unsigned)(xx+3) < 30u) wb_[(xx+3)*40] = to_tf32(v.w);      \
        }                                                                   \
    } while(0)

    float acc[2][8][4];
    #pragma unroll
    for (int mt = 0; mt < 2; mt++)
        #pragma unroll
        for (int nt = 0; nt < 8; nt++)
            #pragma unroll
            for (int q = 0; q < 4; q++) acc[mt][nt][q] = 0.f;

    // prologue
    FILL_WIN(0);
    LDG_B(0, 0);
    STS_B(0);
    __syncthreads();

    for (int icg = 0; icg < 8; icg++) {
        if (icg) { FILL_WIN(icg); __syncthreads(); }
        for (int tap = 0; tap < 9; tap++) {
            const int chunk = icg*9 + tap;
            const int buf   = chunk & 1;
            const bool more = (chunk < 71);
            if (more) {
                int nc = chunk + 1;
                int ni = nc / 9;
                LDG_B(ni, nc - 9*ni);
            }
            // embedded zero-fill of the 8x28 output patch (all 512 oc)
            #pragma unroll
            for (int zz = 0; zz < 2; zz++) {
                int v = (chunk*2 + zz)*256 + tid;
                if (v < 28672) {
                    int oc  = v / 56;
                    int rem = v - oc*56;
                    int rr  = rem / 7;
                    int c4  = rem - rr*7;
                    *(float4*)(outb + (size_t)oc*NPIX + (r0+rr)*HW + xoff + c4*4)
                        = make_float4(0.f,0.f,0.f,0.f);
                }
            }
            // compute: warp w8 -> output row r0+w8, cols xoff..xoff+27
            const int dy = tap/3 - 1;
            const int dx = tap - 3*(tap/3) - 1;
            const float* Ab = win + ((w8 + dy + 1)*XP + (dx + 1) + g)*40 + 2*tq;
            const float* Bb = Bst + buf*BSTG + g*40 + 2*tq;
            #pragma unroll
            for (int ks = 0; ks < 4; ks++) {
                uint2 bf[8];
                #pragma unroll
                for (int nt = 0; nt < 8; nt++)
                    bf[nt] = *(const uint2*)(Bb + nt*320 + ks*8);
                #pragma unroll
                for (int mt = 0; mt < 2; mt++) {
                    uint2 aA = *(const uint2*)(Ab + mt*640 + ks*8);
                    uint2 aB = *(const uint2*)(Ab + mt*640 + 320 + ks*8);
                    #pragma unroll
                    for (int nt = 0; nt < 8; nt++) {
                        asm volatile(
                          "mma.sync.aligned.m16n8k8.row.col.f32.tf32.tf32.f32 "
                          "{%0,%1,%2,%3}, {%4,%5,%6,%7}, {%8,%9}, {%0,%1,%2,%3};"
                          : "+f"(acc[mt][nt][0]), "+f"(acc[mt][nt][1]),
                            "+f"(acc[mt][nt][2]), "+f"(acc[mt][nt][3])
                          : "r"(aA.x), "r"(aB.x), "r"(aA.y), "r"(aB.y),
                            "r"(bf[nt].x), "r"(bf[nt].y));
                    }
                }
            }
            if (more) STS_B(buf ^ 1);
            __syncthreads();
        }
    }

    // epilogue: warp w8 -> output row r0+w8, cols xoff + (mt*16+g), valid < 28
    {
        float* orow = outb + (r0 + w8)*HW + xoff;
        #pragma unroll
        for (int nt = 0; nt < 8; nt++) {
            #pragma unroll
            for (int hh = 0; hh < 2; hh++) {
                int n = nt*8 + tq*2 + hh;
                float* op = orow + (size_t)s_sel[n]*NPIX;
                float bi = s_bias[n];
                #pragma unroll
                for (int mt = 0; mt < 2; mt++) {
                    int col = mt*16 + g;
                    if (col < 28) {
                        op[col]   = acc[mt][nt][hh]   + bi;
                        int col8 = col + 8;
                        if (col8 < 28)
                            op[col8] = acc[mt][nt][2+hh] + bi;
                    }
                }
            }
        }
    }
}

// ---------------------------------------------------------------------------
extern "C" void kernel_launch(void* const* d_in, const int* in_sizes, int n_in,
                              void* d_out, int out_size) {
    const float* x    = (const float*)d_in[0];   // [32,256,56,56]
    const float* w    = (const float*)d_in[1];   // [512,256,3,3]
    const float* bias = (const float*)d_in[2];   // [512]
    const float* rw   = (const float*)d_in[3];   // [512,256]
    const float* rb   = (const float*)d_in[4];   // [512]
    float* out = (float*)d_out;                  // [32,512,56,56]

    cudaFuncSetAttribute(conv_mma, cudaFuncAttributeMaxDynamicSharedMemorySize,
                         SMEMB);

    pool_kernel<<<BB*IC, 128>>>(x);
    router_kernel<<<BB, OC>>>(rw, rb);
    conv_mma<<<dim3(7, 2, BB), 256, SMEMB>>>(x, w, bias, out);
}

// round 10
// speedup vs baseline: 1.5413x; 1.2047x over previous
#include <cuda_runtime.h>
#include <cstdint>

#define BB 32
#define IC 256
#define OC 512
#define HW 56
#define NPIX (HW*HW)
#define NF 64

// scratch (no allocations allowed)
__device__ float g_pooled[BB*IC];
__device__ int   g_sel[BB*NF];
__device__ __align__(16) float g_wt[OC*IC*9];   // rna-tf32 weights

__device__ __forceinline__ float to_tf32(float v){
    float o; asm("cvt.rna.tf32.f32 %0, %1;" : "=f"(o) : "f"(v)); return o;
}
__device__ __forceinline__ uint32_t smem_u32(const void* p){
    uint32_t a;
    asm("{ .reg .u64 t; cvta.to.shared.u64 t, %1; cvt.u32.u64 %0, t; }"
        : "=r"(a) : "l"(p));
    return a;
}
#define CPA(dst, src, szr) \
    asm volatile("cp.async.ca.shared.global [%0], [%1], 16, %2;" \
                 :: "r"(dst), "l"(src), "r"(szr))

// ---------------------------------------------------------------------------
// Kernel 1: global average pool + weight tf32 pre-conversion (folded in).
// ---------------------------------------------------------------------------
__global__ void pool_kernel(const float* __restrict__ x,
                            const float* __restrict__ w) {
    int plane = blockIdx.x;
    // fold: blocks 0..2303 also convert one float4 of weights each thread
    if (blockIdx.x < 2304) {
        int i = blockIdx.x*128 + threadIdx.x;      // 294912 float4 total
        float4 v = ((const float4*)w)[i];
        v.x = to_tf32(v.x); v.y = to_tf32(v.y);
        v.z = to_tf32(v.z); v.w = to_tf32(v.w);
        ((float4*)g_wt)[i] = v;
    }
    const float4* p = (const float4*)(x + (size_t)plane * NPIX);
    float s = 0.f;
    for (int i = threadIdx.x; i < NPIX/4; i += 128) {
        float4 v = p[i];
        s += (v.x + v.y) + (v.z + v.w);
    }
    #pragma unroll
    for (int o = 16; o; o >>= 1) s += __shfl_down_sync(0xffffffffu, s, o);
    __shared__ float ws[4];
    if ((threadIdx.x & 31) == 0) ws[threadIdx.x >> 5] = s;
    __syncthreads();
    if (threadIdx.x == 0)
        g_pooled[plane] = (ws[0] + ws[1] + ws[2] + ws[3]) * (1.0f / NPIX);
}

// ---------------------------------------------------------------------------
// Kernel 2: router linear + exact top-64 (tie-break by index, = jax top_k).
// ---------------------------------------------------------------------------
__global__ void router_kernel(const float* __restrict__ rw,
                              const float* __restrict__ rb) {
    int b  = blockIdx.x;
    int oc = threadIdx.x;
    __shared__ float ps[IC];
    __shared__ float rs[OC];
    __shared__ int   cnt;
    if (oc < IC) ps[oc] = g_pooled[b*IC + oc];
    if (oc == 0) cnt = 0;
    __syncthreads();
    float s = rb[oc];
    const float* wrow = rw + (size_t)oc * IC;
    #pragma unroll 8
    for (int i = 0; i < IC; i++) s += ps[i] * wrow[i];
    rs[oc] = s;
    __syncthreads();
    int rank = 0;
    for (int j = 0; j < OC; j++) {
        float v = rs[j];
        rank += (v > s) || (v == s && j < oc);
    }
    if (rank < NF) {
        int pos = atomicAdd(&cnt, 1);
        g_sel[b*NF + pos] = oc;
    }
}

// ---------------------------------------------------------------------------
// Kernel 3: tf32 mma.sync implicit-GEMM conv on the 64 selected channels.
// CTA = (b, 8-row slab, 28-col half-tile).  Grid (7, 2, 32), 256 threads.
// Per ic-group (16 ics): cp.async-stage input window [y10][ic16][x pitch44]
// (zero-fill via src-size trick) and B = raw rows of g_wt for ALL 9 taps
// [oc64][pitch156].  Then 9 taps x 32 mma with no intra-group barriers.
// A fragments rna-cvt'd at consume time.  2 CTAs/SM, 32 barriers total.
// ---------------------------------------------------------------------------
#define NICG 16
#define WPITCH 44
#define WIN_FLOATS (10*16*WPITCH)      // 7040
#define BPITCH 156
#define B_FLOATS (64*BPITCH)           // 9984
#define SMEMB ((WIN_FLOATS + B_FLOATS)*4)

__global__ __launch_bounds__(256, 2)
void conv_mma(const float* __restrict__ x,
              const float* __restrict__ bias, float* __restrict__ out)
{
    extern __shared__ float sm[];
    float* win = sm;
    float* Bsm = sm + WIN_FLOATS;
    __shared__ int   s_sel[64];
    __shared__ float s_bias[64];

    const int tid  = threadIdx.x;
    const int w8   = tid >> 5;            // warp id == output row within slab
    const int lane = tid & 31;
    const int g    = lane >> 2;           // mma groupID
    const int tq   = lane & 3;            // mma threadID-in-group
    const int r0   = blockIdx.x * 8;
    const int xoff = blockIdx.y * 28;
    const int b    = blockIdx.z;

    if (tid < 64) {
        int sc = g_sel[b*NF + tid];
        s_sel[tid]  = sc;
        s_bias[tid] = bias[sc];
    }
    __syncthreads();

    const float* xb   = x + (size_t)b*IC*NPIX;
    float*       outb = out + (size_t)b*OC*NPIX;
    const uint32_t win_s = smem_u32(win);
    const uint32_t b_s   = smem_u32(Bsm);

    float acc[2][8][4];
    #pragma unroll
    for (int mt = 0; mt < 2; mt++)
        #pragma unroll
        for (int nt = 0; nt < 8; nt++)
            #pragma unroll
            for (int q = 0; q < 4; q++) acc[mt][nt][q] = 0.f;

    for (int icg = 0; icg < NICG; icg++) {
        // ---- stage phase: window + B via cp.async ----
        {
            const float* xp = xb + (size_t)icg*16*NPIX;
            for (int i = tid; i < 1600; i += 256) {
                int j  = i % 10;
                int t  = i / 10;              // y*16 + ic
                int ic = t & 15;
                int y  = t >> 4;
                int gy  = r0 - 1 + y;
                int gx4 = xoff - 4 + 4*j;
                bool v = ((unsigned)gy < (unsigned)HW) &&
                         ((unsigned)gx4 <= (unsigned)(HW-4));
                const float* src = v ? (xp + (size_t)ic*NPIX + gy*HW + gx4) : xp;
                uint32_t dst = win_s + (uint32_t)(t*WPITCH + 4*j)*4u;
                CPA(dst, src, v ? 16 : 0);
            }
            for (int i = tid; i < 2304; i += 256) {
                int row = i / 36;             // oc slot 0..63
                int v   = i - row*36;
                const float* src = g_wt + (size_t)s_sel[row]*(IC*9)
                                        + icg*144 + 4*v;
                uint32_t dst = b_s + (uint32_t)(row*BPITCH + 4*v)*4u;
                CPA(dst, src, 16);
            }
            asm volatile("cp.async.wait_all;" ::: "memory");
        }
        __syncthreads();

        // ---- compute phase: 9 taps, no barriers ----
        #pragma unroll
        for (int tap = 0; tap < 9; tap++) {
            // embedded zero-fill of the 8x28 output patch (all 512 oc)
            {
                int v = (icg*9 + tap)*256 + tid;
                if (v < 28672) {
                    int oc  = v / 56;
                    int rem = v - oc*56;
                    int rr  = rem / 7;
                    int c4  = rem - rr*7;
                    *(float4*)(outb + (size_t)oc*NPIX + (r0+rr)*HW + xoff + c4*4)
                        = make_float4(0.f,0.f,0.f,0.f);
                }
            }
            const int dy = tap/3 - 1;
            const int dx = tap - 3*(tap/3) - 1;
            const float* Ay = win + (w8 + dy + 1)*(16*WPITCH);
            const int sxb = g + dx + 4;
            #pragma unroll
            for (int ks = 0; ks < 2; ks++) {
                const int kof = (8*ks + 2*tq)*9 + tap;
                uint32_t b0[8], b1[8];
                #pragma unroll
                for (int nt = 0; nt < 8; nt++) {
                    const float* bp = Bsm + (nt*8 + g)*BPITCH + kof;
                    b0[nt] = __float_as_uint(bp[0]);
                    b1[nt] = __float_as_uint(bp[9]);
                }
                #pragma unroll
                for (int mt = 0; mt < 2; mt++) {
                    const float* ap = Ay + (8*ks + 2*tq)*WPITCH + sxb + 16*mt;
                    uint32_t a0 = __float_as_uint(to_tf32(ap[0]));
                    uint32_t a1 = __float_as_uint(to_tf32(ap[8]));
                    uint32_t a2 = __float_as_uint(to_tf32(ap[WPITCH]));
                    uint32_t a3 = __float_as_uint(to_tf32(ap[WPITCH+8]));
                    #pragma unroll
                    for (int nt = 0; nt < 8; nt++) {
                        asm volatile(
                          "mma.sync.aligned.m16n8k8.row.col.f32.tf32.tf32.f32 "
                          "{%0,%1,%2,%3}, {%4,%5,%6,%7}, {%8,%9}, {%0,%1,%2,%3};"
                          : "+f"(acc[mt][nt][0]), "+f"(acc[mt][nt][1]),
                            "+f"(acc[mt][nt][2]), "+f"(acc[mt][nt][3])
                          : "r"(a0), "r"(a1), "r"(a2), "r"(a3),
                            "r"(b0[nt]), "r"(b1[nt]));
                    }
                }
            }
        }
        __syncthreads();   // window/B consumed; safe to restage
    }

    // epilogue: warp w8 -> output row r0+w8, cols xoff + (mt*16+g), valid < 28
    {
        float* orow = outb + (r0 + w8)*HW + xoff;
        #pragma unroll
        for (int nt = 0; nt < 8; nt++) {
            #pragma unroll
            for (int hh = 0; hh < 2; hh++) {
                int n = nt*8 + tq*2 + hh;
                float* op = orow + (size_t)s_sel[n]*NPIX;
                float bi = s_bias[n];
                #pragma unroll
                for (int mt = 0; mt < 2; mt++) {
                    int col = mt*16 + g;
                    if (col < 28) {
                        op[col] = acc[mt][nt][hh] + bi;
                        int col8 = col + 8;
                        if (col8 < 28)
                            op[col8] = acc[mt][nt][2+hh] + bi;
                    }
                }
            }
        }
    }
}

// ---------------------------------------------------------------------------
extern "C" void kernel_launch(void* const* d_in, const int* in_sizes, int n_in,
                              void* d_out, int out_size) {
    const float* x    = (const float*)d_in[0];   // [32,256,56,56]
    const float* w    = (const float*)d_in[1];   // [512,256,3,3]
    const float* bias = (const float*)d_in[2];   // [512]
    const float* rw   = (const float*)d_in[3];   // [512,256]
    const float* rb   = (const float*)d_in[4];   // [512]
    float* out = (float*)d_out;                  // [32,512,56,56]

    cudaFuncSetAttribute(conv_mma, cudaFuncAttributeMaxDynamicSharedMemorySize,
                         SMEMB);

    pool_kernel<<<BB*IC, 128>>>(x, w);
    router_kernel<<<BB, OC>>>(rw, rb);
    conv_mma<<<dim3(7, 2, BB), 256, SMEMB>>>(x, bias, out);
}

// round 11
// speedup vs baseline: 2.3142x; 1.5014x over previous
#include <cuda_runtime.h>
#include <cuda_fp16.h>
#include <cstdint>

#define BB 32
#define IC 256
#define OC 512
#define HW 56
#define NPIX (HW*HW)
#define NF 64

// scratch (no allocations allowed)
__device__ float g_pp[BB*IC*56];                         // pool partials [b][ic][y]
__device__ int   g_sel[BB*NF];
__device__ __align__(16) unsigned short g_xh[(size_t)BB*56*56*IC]; // NHWC fp16
__device__ __align__(16) unsigned short g_wh[OC*9*IC];   // [oc][tap][ic] fp16

__device__ __forceinline__ uint32_t smem_u32(const void* p){
    uint32_t a;
    asm("{ .reg .u64 t; cvta.to.shared.u64 t, %1; cvt.u32.u64 %0, t; }"
        : "=r"(a) : "l"(p));
    return a;
}
#define CPA(dst, src, szr) \
    asm volatile("cp.async.ca.shared.global [%0], [%1], 16, %2;" \
                 :: "r"(dst), "l"(src), "r"(szr))

// ---------------------------------------------------------------------------
// Kernel 1: prep.  Blocks 0..511: weight transpose+fp16.  Blocks 512..2303:
// x NCHW->NHWC fp16 transpose for one (b,y) row + pooling partial sums.
// ---------------------------------------------------------------------------
__global__ void prep_kernel(const float* __restrict__ x,
                            const float* __restrict__ w) {
    __shared__ float s[128][57];
    const int tid = threadIdx.x, lane = tid & 31, wp = tid >> 5;

    if (blockIdx.x < 512) {                      // ---- weights ----
        int oc = blockIdx.x;
        float* ws = &s[0][0];                    // 2304 floats
        const float4* src = (const float4*)(w + (size_t)oc*2304);
        for (int i = tid; i < 576; i += 256) ((float4*)ws)[i] = src[i];
        __syncthreads();
        for (int j = tid; j < 1152; j += 256) {  // half2 units
            int tap = j >> 7, icp = j & 127;
            __half2 h = __floats2half2_rn(ws[(2*icp)*9 + tap],
                                          ws[(2*icp+1)*9 + tap]);
            ((__half2*)g_wh)[(size_t)oc*1152 + tap*128 + icp] = h;
        }
        return;
    }
    const int bid = blockIdx.x - 512;
    const int b = bid / 56, y = bid - 56*b;
    const float* xp = x + (size_t)b*IC*NPIX + y*HW;

    for (int p = 0; p < 2; p++) {
        #pragma unroll 4
        for (int i = 0; i < 16; i++) {
            int icl = wp*16 + i;
            int ic  = p*128 + icl;
            const float* row = xp + (size_t)ic*NPIX;
            float v0 = row[lane];
            float v1 = (lane < 24) ? row[lane+32] : 0.f;
            s[icl][lane] = v0;
            if (lane < 24) s[icl][lane+32] = v1;
            float sum = v0 + v1;
            #pragma unroll
            for (int o = 16; o; o >>= 1) sum += __shfl_down_sync(~0u, sum, o);
            if (lane == 0) g_pp[((size_t)b*IC + ic)*56 + y] = sum;
        }
        __syncthreads();
        for (int j = tid; j < 3584; j += 256) {
            int xx = j >> 6, icp = j & 63;
            __half2 h = __floats2half2_rn(s[2*icp][xx], s[2*icp+1][xx]);
            ((__half2*)g_xh)[((size_t)(b*56+y)*56 + xx)*128 + p*64 + icp] = h;
        }
        __syncthreads();
    }
}

// ---------------------------------------------------------------------------
// Kernel 2: router linear + exact top-64 (tie-break by index, = jax top_k).
// ---------------------------------------------------------------------------
__global__ void router_kernel(const float* __restrict__ rw,
                              const float* __restrict__ rb) {
    int b  = blockIdx.x;
    int oc = threadIdx.x;
    __shared__ float ps[IC];
    __shared__ float rs[OC];
    __shared__ int   cnt;
    if (oc < IC) {
        const float* pp = g_pp + ((size_t)b*IC + oc)*56;
        float sum = 0.f;
        #pragma unroll 8
        for (int y = 0; y < 56; y++) sum += pp[y];
        ps[oc] = sum * (1.0f/NPIX);
    }
    if (oc == 0) cnt = 0;
    __syncthreads();
    float s = rb[oc];
    const float* wrow = rw + (size_t)oc * IC;
    #pragma unroll 8
    for (int i = 0; i < IC; i++) s += ps[i] * wrow[i];
    rs[oc] = s;
    __syncthreads();
    int rank = 0;
    for (int j = 0; j < OC; j++) {
        float v = rs[j];
        rank += (v > s) || (v == s && j < oc);
    }
    if (rank < NF) {
        int pos = atomicAdd(&cnt, 1);
        g_sel[b*NF + pos] = oc;
    }
}

// ---------------------------------------------------------------------------
// Kernel 3: fp16 m16n8k16 implicit-GEMM conv on the 64 selected channels.
// CTA = (b, 8-row slab, 28-col half).  Grid (7, 2, 32), 256 threads, 2/SM.
// 16 groups of 16 ic.  2-stage cp.async pipeline (one barrier per group).
// A smem [y10][x34][ic16 +pad8] (48B slots, conflict-free), B smem
// [oc64][tap9][ic16 +pad] (304B rows, conflict-free).  Zero-fill embedded.
// ---------------------------------------------------------------------------
#define WSLOT 24
#define WXN   34
#define WINH  (10*WXN*WSLOT)     // 8160 halves
#define BPH   152
#define BH    (64*BPH)           // 9728 halves
#define STGH  (WINH + BH)        // 17888 halves
#define SMEMB (2*STGH*2)         // 71552 bytes

__global__ __launch_bounds__(256, 2)
void conv_mma(const float* __restrict__ bias, float* __restrict__ out)
{
    extern __shared__ unsigned short smh[];
    __shared__ int   s_sel[64];
    __shared__ float s_bias[64];

    const int tid  = threadIdx.x;
    const int w8   = tid >> 5;            // warp id == output row within slab
    const int lane = tid & 31;
    const int g    = lane >> 2;
    const int tq   = lane & 3;
    const int r0   = blockIdx.x * 8;
    const int xoff = blockIdx.y * 28;
    const int b    = blockIdx.z;

    if (tid < 64) {
        int sc = g_sel[b*NF + tid];
        s_sel[tid]  = sc;
        s_bias[tid] = bias[sc];
    }
    __syncthreads();

    float* outb = out + (size_t)b*OC*NPIX;
    const uint32_t base_s = smem_u32(smh);

    // ---- stage one 16-ic group into buffer sb ----
    #define STAGE(grp_, sb_) do {                                           \
        uint32_t ws_ = base_s + (sb_)*(STGH*2);                             \
        uint32_t bs_ = ws_ + WINH*2;                                        \
        for (int i = tid; i < 680; i += 256) {                              \
            int ch = i & 1, t = i >> 1;                                     \
            int xw = t % 34, yy = t / 34;                                   \
            int gy = r0 + yy - 1, gx = xoff + xw - 1;                       \
            bool val = ((unsigned)gy < (unsigned)HW) &&                     \
                       ((unsigned)gx < (unsigned)HW);                       \
            const unsigned short* src = val ?                               \
                (g_xh + (((size_t)(b*56+gy)*56+gx)*256 + (grp_)*16 + ch*8)) \
                : g_xh;                                                     \
            CPA(ws_ + (uint32_t)(t*WSLOT + ch*8)*2u, src, val ? 16 : 0);    \
        }                                                                   \
        for (int i = tid; i < 1152; i += 256) {                             \
            int row = i / 18, v = i - row*18;                               \
            int tap = v >> 1, ch = v & 1;                                   \
            const unsigned short* src = g_wh +                              \
                (((size_t)s_sel[row]*9 + tap)*256 + (grp_)*16 + ch*8);      \
            CPA(bs_ + (uint32_t)(row*BPH + tap*16 + ch*8)*2u, src, 16);     \
        }                                                                   \
        asm volatile("cp.async.commit_group;" ::: "memory");                \
    } while(0)

    float acc[2][8][4];
    #pragma unroll
    for (int mt = 0; mt < 2; mt++)
        #pragma unroll
        for (int nt = 0; nt < 8; nt++)
            #pragma unroll
            for (int q = 0; q < 4; q++) acc[mt][nt][q] = 0.f;

    STAGE(0, 0);

    for (int grp = 0; grp < 16; grp++) {
        asm volatile("cp.async.wait_group 0;" ::: "memory");
        __syncthreads();
        if (grp + 1 < 16) STAGE(grp + 1, (grp + 1) & 1);

        const unsigned short* win = smh + (grp & 1)*STGH;
        const unsigned short* Bs  = win + WINH;

        #pragma unroll
        for (int tap = 0; tap < 9; tap++) {
            // embedded zero-fill of the 8x28 output patch (all 512 oc)
            {
                int v = (grp*9 + tap)*256 + tid;
                if (v < 28672) {
                    int oc  = v / 56;
                    int rem = v - oc*56;
                    int rr  = rem / 7;
                    int c4  = rem - rr*7;
                    *(float4*)(outb + (size_t)oc*NPIX + (r0+rr)*HW + xoff + c4*4)
                        = make_float4(0.f,0.f,0.f,0.f);
                }
            }
            const int dy = tap/3 - 1;
            const int dx = tap - 3*(tap/3) - 1;

            uint32_t bb0[8], bb1[8];
            #pragma unroll
            for (int nt = 0; nt < 8; nt++) {
                const unsigned short* bp = Bs + (nt*8 + g)*BPH + tap*16 + 2*tq;
                bb0[nt] = *(const uint32_t*)bp;
                bb1[nt] = *(const uint32_t*)(bp + 8);
            }
            #pragma unroll
            for (int mt = 0; mt < 2; mt++) {
                const unsigned short* ap = win +
                    ((w8 + dy + 1)*WXN + mt*16 + g + dx + 1)*WSLOT + 2*tq;
                uint32_t a0 = *(const uint32_t*)ap;
                uint32_t a2 = *(const uint32_t*)(ap + 8);
                uint32_t a1 = *(const uint32_t*)(ap + 8*WSLOT);
                uint32_t a3 = *(const uint32_t*)(ap + 8*WSLOT + 8);
                #pragma unroll
                for (int nt = 0; nt < 8; nt++) {
                    asm volatile(
                      "mma.sync.aligned.m16n8k16.row.col.f32.f16.f16.f32 "
                      "{%0,%1,%2,%3}, {%4,%5,%6,%7}, {%8,%9}, {%0,%1,%2,%3};"
                      : "+f"(acc[mt][nt][0]), "+f"(acc[mt][nt][1]),
                        "+f"(acc[mt][nt][2]), "+f"(acc[mt][nt][3])
                      : "r"(a0), "r"(a1), "r"(a2), "r"(a3),
                        "r"(bb0[nt]), "r"(bb1[nt]));
                }
            }
        }
        __syncthreads();   // done reading buf grp&1; next STAGE may overwrite
    }

    // epilogue: warp w8 -> output row r0+w8, cols xoff + (mt*16+g), valid < 28
    {
        float* orow = outb + (r0 + w8)*HW + xoff;
        #pragma unroll
        for (int nt = 0; nt < 8; nt++) {
            #pragma unroll
            for (int hh = 0; hh < 2; hh++) {
                int n = nt*8 + tq*2 + hh;
                float* op = orow + (size_t)s_sel[n]*NPIX;
                float bi = s_bias[n];
                #pragma unroll
                for (int mt = 0; mt < 2; mt++) {
                    int col = mt*16 + g;
                    if (col < 28) {
                        op[col] = acc[mt][nt][hh] + bi;
                        int col8 = col + 8;
                        if (col8 < 28)
                            op[col8] = acc[mt][nt][2+hh] + bi;
                    }
                }
            }
        }
    }
}

// ---------------------------------------------------------------------------
extern "C" void kernel_launch(void* const* d_in, const int* in_sizes, int n_in,
                              void* d_out, int out_size) {
    const float* x    = (const float*)d_in[0];   // [32,256,56,56]
    const float* w    = (const float*)d_in[1];   // [512,256,3,3]
    const float* bias = (const float*)d_in[2];   // [512]
    const float* rw   = (const float*)d_in[3];   // [512,256]
    const float* rb   = (const float*)d_in[4];   // [512]
    float* out = (float*)d_out;                  // [32,512,56,56]

    cudaFuncSetAttribute(conv_mma, cudaFuncAttributeMaxDynamicSharedMemorySize,
                         SMEMB);

    prep_kernel<<<512 + BB*56, 256>>>(x, w);
    router_kernel<<<BB, OC>>>(rw, rb);
    conv_mma<<<dim3(7, 2, BB), 256, SMEMB>>>(bias, out);
}